// round 4
// baseline (speedup 1.0000x reference)
#include <cuda_runtime.h>
#include <cstdint>
#include <cstddef>

// Problem constants
#define DMODEL 1024
#define SEQ    4096
#define BATCH  4
#define NHEAD  16
#define DK     64
#define M_TOTAL (BATCH * SEQ)   // 16384
#define BH      (BATCH * NHEAD) // 64
#define NCH     16

// ---------------- scratch (static device globals; no allocation) ----------------
__device__ float g_Q[(size_t)M_TOTAL * DMODEL];
__device__ float g_K[(size_t)M_TOTAL * DMODEL];
__device__ float g_V[(size_t)M_TOTAL * DMODEL];
__device__ unsigned short g_xhi[(size_t)M_TOTAL * DMODEL];
__device__ unsigned short g_xlo[(size_t)M_TOTAL * DMODEL];
__device__ unsigned short g_whi[(size_t)DMODEL * DMODEL];
__device__ unsigned short g_wlo[(size_t)DMODEL * DMODEL];
__device__ unsigned short g_ahi[(size_t)M_TOTAL * DMODEL];
__device__ unsigned short g_alo[(size_t)M_TOTAL * DMODEL];
__device__ float g_pKV[(size_t)NCH * BH * DK * DK];
__device__ float g_pKsum[(size_t)NCH * BH * DK];
__device__ float g_KV[(size_t)BH * DK * DK];
__device__ float g_Ksum[(size_t)BH * DK];

// ---------------- helpers ----------------
__device__ __forceinline__ unsigned long long pack2(float x, float y) {
    unsigned long long r;
    asm("mov.b64 %0, {%1, %2};" : "=l"(r) : "f"(x), "f"(y));
    return r;
}
__device__ __forceinline__ void unpack2(unsigned long long v, float& x, float& y) {
    asm("mov.b64 {%0, %1}, %2;" : "=f"(x), "=f"(y) : "l"(v));
}
__device__ __forceinline__ void ffma2(unsigned long long& d,
                                      unsigned long long a,
                                      unsigned long long b) {
    asm("fma.rn.f32x2 %0, %1, %2, %0;" : "+l"(d) : "l"(a), "l"(b));
}
__device__ __forceinline__ uint32_t prmt7632(uint32_t a, uint32_t b) {
    uint32_t r;
    asm("prmt.b32 %0, %1, %2, 0x7632;" : "=r"(r) : "r"(a), "r"(b));
    return r;
}
__device__ __forceinline__ uint32_t smem_u32(const void* p) {
    uint32_t a;
    asm("{ .reg .u64 t; cvta.to.shared.u64 t, %1; cvt.u32.u64 %0, t; }" : "=r"(a) : "l"(p));
    return a;
}
// split float4 -> hi bf16x2 pair (truncation: exact residual) + lo bf16x2 pair (RN)
__device__ __forceinline__ void cvtsplit4(const float4& v, uint2& hi, uint2& lo) {
    const uint32_t bx = __float_as_uint(v.x), by = __float_as_uint(v.y);
    const uint32_t bz = __float_as_uint(v.z), bw = __float_as_uint(v.w);
    hi.x = prmt7632(bx, by);
    hi.y = prmt7632(bz, bw);
    const float rx = v.x - __uint_as_float(bx & 0xffff0000u);
    const float ry = v.y - __uint_as_float(by & 0xffff0000u);
    const float rz = v.z - __uint_as_float(bz & 0xffff0000u);
    const float rw = v.w - __uint_as_float(bw & 0xffff0000u);
    asm("cvt.rn.bf16x2.f32 %0, %1, %2;" : "=r"(lo.x) : "f"(ry), "f"(rx));
    asm("cvt.rn.bf16x2.f32 %0, %1, %2;" : "=r"(lo.y) : "f"(rw), "f"(rz));
}
__device__ __forceinline__ void split1(float x, unsigned short& h, unsigned short& l) {
    const uint32_t b = __float_as_uint(x);
    h = (unsigned short)(b >> 16);
    const float r = x - __uint_as_float(b & 0xffff0000u);
    asm("cvt.rn.bf16.f32 %0, %1;" : "=h"(l) : "f"(r));
}

#define LDSM_X4(r0, r1, r2, r3, addr) \
    asm volatile("ldmatrix.sync.aligned.m8n8.x4.shared.b16 {%0,%1,%2,%3}, [%4];" \
                 : "=r"(r0), "=r"(r1), "=r"(r2), "=r"(r3) : "r"(addr))

#define MMA_BF16(d, a, b0, b1) \
    asm volatile("mma.sync.aligned.m16n8k16.row.col.f32.bf16.bf16.f32 " \
                 "{%0,%1,%2,%3}, {%4,%5,%6,%7}, {%8,%9}, {%0,%1,%2,%3};" \
                 : "+f"((d)[0]), "+f"((d)[1]), "+f"((d)[2]), "+f"((d)[3]) \
                 : "r"((a)[0]), "r"((a)[1]), "r"((a)[2]), "r"((a)[3]), \
                   "r"(b0), "r"(b1))

__device__ __forceinline__ void cpasync16(uint32_t saddr, const void* g) {
    asm volatile("cp.async.ca.shared.global [%0], [%1], 16;" :: "r"(saddr), "l"(g) : "memory");
}

// ---------------- convert: fp32 -> (hi, lo) bf16 arrays ----------------
__global__ void __launch_bounds__(256)
cvt_split_kernel(const float* __restrict__ in, unsigned short* __restrict__ hi,
                 unsigned short* __restrict__ lo, int n4)
{
    const int i = blockIdx.x * 256 + threadIdx.x;
    if (i < n4) {
        float4 v = ((const float4*)in)[i];
        uint2 h, l;
        cvtsplit4(v, h, l);
        ((uint2*)hi)[i] = h;
        ((uint2*)lo)[i] = l;
    }
}

// ---------------- HMMA GEMM with cp.async pipeline ----------------
// C[m,n] = sum_k A[m,k] * W[n,k]; A,W pre-split into hi/lo bf16.
// CTA 128x128, 512 threads (16 warps, warp tile 32x32), K-stage 32, 4-stage ring.
#define KSTAGE 32
#define NKIT   (DMODEL / KSTAGE)           // 32
#define ROWB   80                          // smem row stride (bytes): conflict-free ldmatrix
#define SUBT   (128 * ROWB)                // 10240 B per 128x32 bf16 sub-tile
#define STAGEB (4 * SUBT)                  // Ahi, Alo, Bhi, Blo = 40960
#define NSTAGE 4
#define GEMM_SMEM (NSTAGE * STAGEB)        // 163840

template <int MODE>
__global__ void __launch_bounds__(512)
gemm_pipe(const unsigned short* __restrict__ Ahi, const unsigned short* __restrict__ Alo,
          const unsigned short* __restrict__ Bhi, const unsigned short* __restrict__ Blo,
          float* __restrict__ C, const float* __restrict__ bias)
{
    extern __shared__ char smem[];
    const uint32_t sbase = smem_u32(smem);

    const int tid  = threadIdx.x;
    const int wid  = tid >> 5;
    const int lane = tid & 31;
    const int rowBase = blockIdx.y * 128;
    const int colBase = blockIdx.x * 128;

    // warp tile: 32m x 32n; warp grid 4m x 4n
    const int wm = (wid & 3) * 32;
    const int wn = (wid >> 2) * 32;

    const uint32_t aoff = (uint32_t)(wm + (lane & 15)) * ROWB + (uint32_t)(lane >> 4) * 16;
    const uint32_t boff = (uint32_t)(wn + (lane & 7) + ((lane >> 4) << 3)) * ROWB
                        + (uint32_t)((lane >> 3) & 1) * 16;

    // cp.async mapping: thread -> (row, 16B chunk) of each sub-tile
    const int crow = tid >> 2;
    const int c16  = tid & 3;
    const unsigned short* gAh = Ahi + (size_t)(rowBase + crow) * DMODEL + c16 * 8;
    const unsigned short* gAl = Alo + (size_t)(rowBase + crow) * DMODEL + c16 * 8;
    const unsigned short* gBh = Bhi + (size_t)(colBase + crow) * DMODEL + c16 * 8;
    const unsigned short* gBl = Blo + (size_t)(colBase + crow) * DMODEL + c16 * 8;
    const uint32_t soff = (uint32_t)crow * ROWB + (uint32_t)c16 * 16;

    float acc[2][4][4];
#pragma unroll
    for (int i = 0; i < 2; i++)
#pragma unroll
        for (int j = 0; j < 4; j++)
#pragma unroll
            for (int r = 0; r < 4; r++) acc[i][j][r] = 0.f;

    // prologue: issue stages 0..NSTAGE-2
#pragma unroll
    for (int s = 0; s < NSTAGE - 1; s++) {
        const uint32_t st = sbase + s * STAGEB + soff;
        const int kt = s * KSTAGE;
        cpasync16(st,                gAh + kt);
        cpasync16(st + SUBT,         gAl + kt);
        cpasync16(st + 2 * SUBT,     gBh + kt);
        cpasync16(st + 3 * SUBT,     gBl + kt);
        asm volatile("cp.async.commit_group;" ::: "memory");
    }

    for (int it = 0; it < NKIT; ++it) {
        asm volatile("cp.async.wait_group %0;" :: "n"(NSTAGE - 2) : "memory");
        __syncthreads();

        // issue stage it+NSTAGE-1 into the buffer consumed at it-1 (safe post-sync)
        if (it + NSTAGE - 1 < NKIT) {
            const int s = it + NSTAGE - 1;
            const uint32_t st = sbase + (s & (NSTAGE - 1)) * STAGEB + soff;
            const int kt = s * KSTAGE;
            cpasync16(st,            gAh + kt);
            cpasync16(st + SUBT,     gAl + kt);
            cpasync16(st + 2 * SUBT, gBh + kt);
            cpasync16(st + 3 * SUBT, gBl + kt);
            asm volatile("cp.async.commit_group;" ::: "memory");
        }

        const uint32_t slot = sbase + (it & (NSTAGE - 1)) * STAGEB;
        const uint32_t pAh = slot + aoff;
        const uint32_t pAl = slot + SUBT + aoff;
        const uint32_t pBh = slot + 2 * SUBT + boff;
        const uint32_t pBl = slot + 3 * SUBT + boff;

#pragma unroll
        for (int kk = 0; kk < 2; kk++) {
            const uint32_t ko = kk * 32;   // 16 bf16 = 32 bytes
            uint32_t ah[8], al[8], bb[8];
            LDSM_X4(ah[0], ah[1], ah[2], ah[3], pAh + ko);
            LDSM_X4(ah[4], ah[5], ah[6], ah[7], pAh + 16 * ROWB + ko);
            LDSM_X4(al[0], al[1], al[2], al[3], pAl + ko);
            LDSM_X4(al[4], al[5], al[6], al[7], pAl + 16 * ROWB + ko);
            LDSM_X4(bb[0], bb[1], bb[2], bb[3], pBh + ko);
            LDSM_X4(bb[4], bb[5], bb[6], bb[7], pBh + 16 * ROWB + ko);
#pragma unroll
            for (int mt = 0; mt < 2; mt++)
#pragma unroll
                for (int j = 0; j < 4; j++)
                    MMA_BF16(acc[mt][j], ah + mt * 4, bb[j * 2], bb[j * 2 + 1]);
#pragma unroll
            for (int mt = 0; mt < 2; mt++)
#pragma unroll
                for (int j = 0; j < 4; j++)
                    MMA_BF16(acc[mt][j], al + mt * 4, bb[j * 2], bb[j * 2 + 1]);
            LDSM_X4(bb[0], bb[1], bb[2], bb[3], pBl + ko);
            LDSM_X4(bb[4], bb[5], bb[6], bb[7], pBl + 16 * ROWB + ko);
#pragma unroll
            for (int mt = 0; mt < 2; mt++)
#pragma unroll
                for (int j = 0; j < 4; j++)
                    MMA_BF16(acc[mt][j], ah + mt * 4, bb[j * 2], bb[j * 2 + 1]);
        }
    }

    // ---- epilogue ----
    const int lrow = lane >> 2;
    const int lcol = (lane & 3) * 2;
#pragma unroll
    for (int mt = 0; mt < 2; mt++) {
#pragma unroll
        for (int j = 0; j < 4; j++) {
            const int col = colBase + wn + j * 8 + lcol;
#pragma unroll
            for (int half = 0; half < 2; half++) {
                const int row = rowBase + wm + mt * 16 + lrow + half * 8;
                float v0 = acc[mt][j][half * 2 + 0];
                float v1 = acc[mt][j][half * 2 + 1];
                if (MODE == 1) {
                    v0 = (v0 > 0.f) ? (v0 + 1.f) : __expf(v0);
                    v1 = (v1 > 0.f) ? (v1 + 1.f) : __expf(v1);
                } else if (MODE == 2) {
                    v0 += bias[col];
                    v1 += bias[col + 1];
                }
                *(float2*)(C + (size_t)row * DMODEL + col) = make_float2(v0, v1);
            }
        }
    }
}

// ---------------- KV partial: per (bh, chunk) sum_s K^T V over SEQ/NCH s ----------------
__global__ void __launch_bounds__(256)
kv_partial_kernel()
{
    const int bh = blockIdx.x;
    const int ch = blockIdx.y;
    const int b = bh >> 4, h = bh & 15;
    const int tid = threadIdx.x;

    __shared__ float Ksh[16][DK];
    __shared__ float Vsh[16][DK];

    const int e = tid & 63;
    const int dbase = (tid >> 6) * 16;

    unsigned long long acc[8];
    {
        const unsigned long long z = pack2(0.f, 0.f);
#pragma unroll
        for (int i = 0; i < 8; i++) acc[i] = z;
    }
    float ksum = 0.f;

    const int s0 = ch * (SEQ / NCH);
    const size_t base = ((size_t)b * SEQ + s0) * DMODEL + h * DK;
    const int lr = tid >> 4;
    const int lc = (tid & 15) * 4;

    for (int st = 0; st < SEQ / NCH; st += 16) {
        const size_t g = base + (size_t)(st + lr) * DMODEL + lc;
        *(float4*)&Ksh[lr][lc] = *(const float4*)(g_K + g);
        *(float4*)&Vsh[lr][lc] = *(const float4*)(g_V + g);
        __syncthreads();

#pragma unroll
        for (int r = 0; r < 16; r++) {
            const float vv = Vsh[r][e];
            const unsigned long long vvp = pack2(vv, vv);
            const ulonglong2 kA = *(const ulonglong2*)&Ksh[r][dbase];
            const ulonglong2 kB = *(const ulonglong2*)&Ksh[r][dbase + 4];
            const ulonglong2 kC = *(const ulonglong2*)&Ksh[r][dbase + 8];
            const ulonglong2 kD = *(const ulonglong2*)&Ksh[r][dbase + 12];
            ffma2(acc[0], kA.x, vvp); ffma2(acc[1], kA.y, vvp);
            ffma2(acc[2], kB.x, vvp); ffma2(acc[3], kB.y, vvp);
            ffma2(acc[4], kC.x, vvp); ffma2(acc[5], kC.y, vvp);
            ffma2(acc[6], kD.x, vvp); ffma2(acc[7], kD.y, vvp);
        }
        if (tid < 64) {
#pragma unroll
            for (int r = 0; r < 16; r++) ksum += Ksh[r][tid];
        }
        __syncthreads();
    }

    float* pkv = g_pKV + ((size_t)ch * BH + bh) * (DK * DK);
#pragma unroll
    for (int p = 0; p < 8; p++) {
        float v0, v1;
        unpack2(acc[p], v0, v1);
        pkv[(dbase + 2 * p) * DK + e] = v0;
        pkv[(dbase + 2 * p + 1) * DK + e] = v1;
    }
    if (tid < 64) g_pKsum[((size_t)ch * BH + bh) * DK + tid] = ksum;
}

// ---------------- KV reduce ----------------
__global__ void kv_reduce_kernel()
{
    const int idx = blockIdx.x * 256 + threadIdx.x;
    const int NKV = BH * DK * DK;
    if (idx < NKV) {
        float s = 0.f;
#pragma unroll
        for (int ch = 0; ch < NCH; ch++) s += g_pKV[(size_t)ch * NKV + idx];
        g_KV[idx] = s;
    } else if (idx < NKV + BH * DK) {
        const int o = idx - NKV;
        float s = 0.f;
#pragma unroll
        for (int ch = 0; ch < NCH; ch++) s += g_pKsum[(size_t)ch * BH * DK + o];
        g_Ksum[o] = s;
    }
}

// ---------------- attention apply: out = (Q @ KV) / (Q . Ksum + eps), split to hi/lo ----------------
__global__ void __launch_bounds__(256)
attn_kernel()
{
    const int bh = blockIdx.x;
    const int qt = blockIdx.y;
    const int b = bh >> 4, h = bh & 15;
    const int tid = threadIdx.x;

    __shared__ float KVs[DK * DK];
    __shared__ float Qs[DK][DK + 2];
    __shared__ float Ksm[DK];
    __shared__ float rden[DK];

    const size_t base = ((size_t)b * SEQ + qt * DK) * DMODEL + h * DK;

#pragma unroll
    for (int l = 0; l < 16; l++) {
        const int idx = tid + l * 256;
        KVs[idx] = g_KV[(size_t)bh * DK * DK + idx];
        const int q = idx >> 6, d = idx & 63;
        Qs[d][q] = g_Q[base + (size_t)q * DMODEL + d];
    }
    if (tid < DK) Ksm[tid] = g_Ksum[bh * DK + tid];
    __syncthreads();

    if (tid < DK) {
        float s = 0.f;
#pragma unroll
        for (int d = 0; d < DK; d++) s += Qs[d][tid] * Ksm[d];
        rden[tid] = 1.f / (s + 1e-6f);
    }
    __syncthreads();

    const int e = tid & 63;
    const int qg = tid >> 6;

    unsigned long long acc[8];
    {
        const unsigned long long z = pack2(0.f, 0.f);
#pragma unroll
        for (int i = 0; i < 8; i++) acc[i] = z;
    }

#pragma unroll 8
    for (int d = 0; d < DK; d++) {
        const float kv = KVs[d * DK + e];
        const unsigned long long kvp = pack2(kv, kv);
#pragma unroll
        for (int t = 0; t < 8; t++) {
            const unsigned long long qp =
                *(const unsigned long long*)&Qs[d][qg * 16 + 2 * t];
            ffma2(acc[t], qp, kvp);
        }
    }

#pragma unroll
    for (int t = 0; t < 8; t++) {
        float v0, v1;
        unpack2(acc[t], v0, v1);
        const int q0 = qg * 16 + 2 * t;
        v0 *= rden[q0];
        v1 *= rden[q0 + 1];
        unsigned short h0, l0, h1, l1;
        split1(v0, h0, l0);
        split1(v1, h1, l1);
        const size_t i0 = base + (size_t)q0 * DMODEL + e;
        const size_t i1 = base + (size_t)(q0 + 1) * DMODEL + e;
        g_ahi[i0] = h0; g_alo[i0] = l0;
        g_ahi[i1] = h1; g_alo[i1] = l1;
    }
}

// ---------------- launch ----------------
extern "C" void kernel_launch(void* const* d_in, const int* in_sizes, int n_in,
                              void* d_out, int out_size)
{
    const float* query = (const float*)d_in[0];
    const float* key   = (const float*)d_in[1];
    const float* value = (const float*)d_in[2];
    const float* Wq    = (const float*)d_in[3];
    const float* Wk    = (const float*)d_in[4];
    const float* Wv    = (const float*)d_in[5];
    const float* Wo    = (const float*)d_in[6];
    const float* bo    = (const float*)d_in[7];
    float* out = (float*)d_out;
    (void)in_sizes; (void)n_in; (void)out_size;

    float *pQ, *pK, *pV;
    unsigned short *xhi, *xlo, *whi, *wlo, *ahi, *alo;
    cudaGetSymbolAddress((void**)&pQ, g_Q);
    cudaGetSymbolAddress((void**)&pK, g_K);
    cudaGetSymbolAddress((void**)&pV, g_V);
    cudaGetSymbolAddress((void**)&xhi, g_xhi);
    cudaGetSymbolAddress((void**)&xlo, g_xlo);
    cudaGetSymbolAddress((void**)&whi, g_whi);
    cudaGetSymbolAddress((void**)&wlo, g_wlo);
    cudaGetSymbolAddress((void**)&ahi, g_ahi);
    cudaGetSymbolAddress((void**)&alo, g_alo);

    cudaFuncSetAttribute(gemm_pipe<0>, cudaFuncAttributeMaxDynamicSharedMemorySize, GEMM_SMEM);
    cudaFuncSetAttribute(gemm_pipe<1>, cudaFuncAttributeMaxDynamicSharedMemorySize, GEMM_SMEM);
    cudaFuncSetAttribute(gemm_pipe<2>, cudaFuncAttributeMaxDynamicSharedMemorySize, GEMM_SMEM);

    const int n4a = M_TOTAL * DMODEL / 4;   // activations: 4.19M float4
    const int n4w = DMODEL * DMODEL / 4;    // weights: 262K float4
    const int cb = 256;
    const dim3 ggrid(DMODEL / 128, M_TOTAL / 128);   // (8, 128)

    // Q = phi(query @ Wq^T)
    cvt_split_kernel<<<(n4a + cb - 1) / cb, cb>>>(query, xhi, xlo, n4a);
    cvt_split_kernel<<<(n4w + cb - 1) / cb, cb>>>(Wq, whi, wlo, n4w);
    gemm_pipe<1><<<ggrid, 512, GEMM_SMEM>>>(xhi, xlo, whi, wlo, pQ, nullptr);

    // K = phi(key @ Wk^T)
    cvt_split_kernel<<<(n4a + cb - 1) / cb, cb>>>(key, xhi, xlo, n4a);
    cvt_split_kernel<<<(n4w + cb - 1) / cb, cb>>>(Wk, whi, wlo, n4w);
    gemm_pipe<1><<<ggrid, 512, GEMM_SMEM>>>(xhi, xlo, whi, wlo, pK, nullptr);

    // V = value @ Wv^T
    cvt_split_kernel<<<(n4a + cb - 1) / cb, cb>>>(value, xhi, xlo, n4a);
    cvt_split_kernel<<<(n4w + cb - 1) / cb, cb>>>(Wv, whi, wlo, n4w);
    gemm_pipe<0><<<ggrid, 512, GEMM_SMEM>>>(xhi, xlo, whi, wlo, pV, nullptr);

    // linear attention core
    kv_partial_kernel<<<dim3(BH, NCH), 256>>>();
    kv_reduce_kernel<<<(BH * DK * DK + BH * DK + 255) / 256, 256>>>();
    attn_kernel<<<dim3(BH, SEQ / DK), 256>>>();

    // out = attn @ Wo^T + bo
    cvt_split_kernel<<<(n4w + cb - 1) / cb, cb>>>(Wo, whi, wlo, n4w);
    gemm_pipe<2><<<ggrid, 512, GEMM_SMEM>>>(ahi, alo, whi, wlo, out, bo);
}

// round 7
// speedup vs baseline: 1.2868x; 1.2868x over previous
#include <cuda_runtime.h>
#include <cuda_fp16.h>
#include <cstdint>
#include <cstddef>

// Problem constants
#define DMODEL 1024
#define SEQ    4096
#define BATCH  4
#define NHEAD  16
#define DK     64
#define M_TOTAL (BATCH * SEQ)   // 16384
#define BH      (BATCH * NHEAD) // 64
#define NCH     16

// ---------------- scratch (static device globals; no allocation) ----------------
__device__ float g_Q[(size_t)M_TOTAL * DMODEL];
__device__ float g_K[(size_t)M_TOTAL * DMODEL];
__device__ float g_V[(size_t)M_TOTAL * DMODEL];
__device__ unsigned short g_af16[(size_t)M_TOTAL * DMODEL];   // attn output, fp16
__device__ unsigned short g_whi[(size_t)DMODEL * DMODEL];
__device__ unsigned short g_wlo[(size_t)DMODEL * DMODEL];
__device__ float g_pKV[(size_t)NCH * BH * DK * DK];
__device__ float g_pKsum[(size_t)NCH * BH * DK];
__device__ float g_KV[(size_t)BH * DK * DK];
__device__ float g_Ksum[(size_t)BH * DK];

// ---------------- helpers ----------------
__device__ __forceinline__ unsigned long long pack2(float x, float y) {
    unsigned long long r;
    asm("mov.b64 %0, {%1, %2};" : "=l"(r) : "f"(x), "f"(y));
    return r;
}
__device__ __forceinline__ void unpack2(unsigned long long v, float& x, float& y) {
    asm("mov.b64 {%0, %1}, %2;" : "=f"(x), "=f"(y) : "l"(v));
}
__device__ __forceinline__ void ffma2(unsigned long long& d,
                                      unsigned long long a,
                                      unsigned long long b) {
    asm("fma.rn.f32x2 %0, %1, %2, %0;" : "+l"(d) : "l"(a), "l"(b));
}
__device__ __forceinline__ uint32_t smem_u32(const void* p) {
    uint32_t a;
    asm("{ .reg .u64 t; cvta.to.shared.u64 t, %1; cvt.u32.u64 %0, t; }" : "=r"(a) : "l"(p));
    return a;
}
__device__ __forceinline__ uint32_t cvt_h2(float hi_val, float lo_val) {
    uint32_t r;
    asm("cvt.rn.f16x2.f32 %0, %1, %2;" : "=r"(r) : "f"(hi_val), "f"(lo_val));
    return r;   // packs: low half = lo_val, high half = hi_val
}
// 8 fp32 -> 8 fp16 packed in uint4
__device__ __forceinline__ uint4 cvt8h(const float4& a, const float4& b) {
    uint4 r;
    r.x = cvt_h2(a.y, a.x);
    r.y = cvt_h2(a.w, a.z);
    r.z = cvt_h2(b.y, b.x);
    r.w = cvt_h2(b.w, b.z);
    return r;
}

#define LDSM_X4(r0, r1, r2, r3, addr) \
    asm volatile("ldmatrix.sync.aligned.m8n8.x4.shared.b16 {%0,%1,%2,%3}, [%4];" \
                 : "=r"(r0), "=r"(r1), "=r"(r2), "=r"(r3) : "r"(addr))

#define MMA_F16(d, a, b0, b1) \
    asm volatile("mma.sync.aligned.m16n8k16.row.col.f32.f16.f16.f32 " \
                 "{%0,%1,%2,%3}, {%4,%5,%6,%7}, {%8,%9}, {%0,%1,%2,%3};" \
                 : "+f"((d)[0]), "+f"((d)[1]), "+f"((d)[2]), "+f"((d)[3]) \
                 : "r"((a)[0]), "r"((a)[1]), "r"((a)[2]), "r"((a)[3]), \
                   "r"(b0), "r"(b1))

__device__ __forceinline__ void cpasync16(uint32_t saddr, const void* g) {
    asm volatile("cp.async.ca.shared.global [%0], [%1], 16;" :: "r"(saddr), "l"(g) : "memory");
}

// ---------------- weight split: fp32 -> (hi, lo) fp16 ----------------
__global__ void __launch_bounds__(256)
cvt_wsplit_kernel(const float* __restrict__ in, unsigned short* __restrict__ hi,
                  unsigned short* __restrict__ lo, int n4)
{
    const int i = blockIdx.x * 256 + threadIdx.x;
    if (i >= n4) return;
    float4 v = ((const float4*)in)[i];
    float h[4], r[4];
    h[0] = __half2float(__float2half_rn(v.x)); r[0] = v.x - h[0];
    h[1] = __half2float(__float2half_rn(v.y)); r[1] = v.y - h[1];
    h[2] = __half2float(__float2half_rn(v.z)); r[2] = v.z - h[2];
    h[3] = __half2float(__float2half_rn(v.w)); r[3] = v.w - h[3];
    uint2 ph, pl;
    ph.x = cvt_h2(h[1], h[0]); ph.y = cvt_h2(h[3], h[2]);
    pl.x = cvt_h2(r[1], r[0]); pl.y = cvt_h2(r[3], r[2]);
    ((uint2*)hi)[i] = ph;
    ((uint2*)lo)[i] = pl;
}

// ---------------- HMMA GEMM: C[m,n] = sum_k A[m,k] * W[n,k] (+epilogue) ----------------
// A: 1-term fp16 (AHALF ? pre-converted in gmem : converted in-loop from fp32).
// W: 2-term fp16 (pre-split, streamed via cp.async).
// CTA 128x128, 512 threads (16 warps, warp tile 32x32), K-stage 32, 2-slot ring.
#define KSTAGE 32
#define NKIT   (DMODEL / KSTAGE)           // 32
#define ROWB   80                          // smem row stride: conflict-free ldmatrix
#define SUBT   (128 * ROWB)                // 10240 B per 128x32 fp16 sub-tile
#define SLOT   (3 * SUBT)                  // A, Bhi, Blo = 30720
#define GEMM_SMEM (2 * SLOT)               // 61440

template <int MODE, int AHALF>
__global__ void __launch_bounds__(512)
gemm_h2(const void* __restrict__ Asrc,
        const unsigned short* __restrict__ Bhi, const unsigned short* __restrict__ Blo,
        float* __restrict__ C, const float* __restrict__ bias)
{
    extern __shared__ char smem[];
    const uint32_t sbase = smem_u32(smem);

    const int tid  = threadIdx.x;
    const int wid  = tid >> 5;
    const int lane = tid & 31;
    const int rowBase = blockIdx.y * 128;
    const int colBase = blockIdx.x * 128;

    const int wm = (wid & 3) * 32;
    const int wn = (wid >> 2) * 32;

    const uint32_t aoff = (uint32_t)(wm + (lane & 15)) * ROWB + (uint32_t)(lane >> 4) * 16;
    const uint32_t boff = (uint32_t)(wn + (lane & 7) + ((lane >> 4) << 3)) * ROWB
                        + (uint32_t)((lane >> 3) & 1) * 16;

    // staging map: thread -> (row, 16B chunk)
    const int crow = tid >> 2;
    const int c16  = tid & 3;
    const float* gA32 = (const float*)Asrc + (size_t)(rowBase + crow) * DMODEL + c16 * 8;
    const unsigned short* gA16 = (const unsigned short*)Asrc
                               + (size_t)(rowBase + crow) * DMODEL + c16 * 8;
    const unsigned short* gBh = Bhi + (size_t)(colBase + crow) * DMODEL + c16 * 8;
    const unsigned short* gBl = Blo + (size_t)(colBase + crow) * DMODEL + c16 * 8;
    const uint32_t soff = (uint32_t)crow * ROWB + (uint32_t)c16 * 16;

    float acc[2][4][4];
#pragma unroll
    for (int i = 0; i < 2; i++)
#pragma unroll
        for (int j = 0; j < 4; j++)
#pragma unroll
            for (int r = 0; r < 4; r++) acc[i][j][r] = 0.f;

    // ---- prologue: stage 0 ----
    {
        cpasync16(sbase + SUBT + soff,     gBh);
        cpasync16(sbase + 2 * SUBT + soff, gBl);
        if (AHALF) {
            cpasync16(sbase + soff, gA16);
        } else {
            float4 a0 = *(const float4*)gA32;
            float4 a1 = *(const float4*)(gA32 + 4);
            *(uint4*)(smem + soff) = cvt8h(a0, a1);
        }
        asm volatile("cp.async.commit_group;" ::: "memory");
        asm volatile("cp.async.wait_group 0;" ::: "memory");
    }
    __syncthreads();

    for (int it = 0; it < NKIT; ++it) {
        const int s = it & 1;
        const uint32_t slot = sbase + s * SLOT;

        // ---- prefetch stage it+1 into the other slot (safe: last read at it-1, synced) ----
        float4 na0, na1;
        if (it + 1 < NKIT) {
            const int kt = (it + 1) * KSTAGE;
            const uint32_t nslot = sbase + (s ^ 1) * SLOT;
            cpasync16(nslot + SUBT + soff,     gBh + kt);
            cpasync16(nslot + 2 * SUBT + soff, gBl + kt);
            if (AHALF) {
                cpasync16(nslot + soff, gA16 + kt);
            } else {
                na0 = *(const float4*)(gA32 + kt);
                na1 = *(const float4*)(gA32 + kt + 4);
            }
            asm volatile("cp.async.commit_group;" ::: "memory");
        }

        // ---- compute current slot ----
        const uint32_t pA  = slot + aoff;
        const uint32_t pBh = slot + SUBT + boff;
        const uint32_t pBl = slot + 2 * SUBT + boff;

#pragma unroll
        for (int kk = 0; kk < 2; kk++) {
            const uint32_t ko = kk * 32;   // 16 fp16 = 32 bytes
            uint32_t ah[8], bh[8], bl[8];
            LDSM_X4(ah[0], ah[1], ah[2], ah[3], pA + ko);
            LDSM_X4(ah[4], ah[5], ah[6], ah[7], pA + 16 * ROWB + ko);
            LDSM_X4(bh[0], bh[1], bh[2], bh[3], pBh + ko);
            LDSM_X4(bh[4], bh[5], bh[6], bh[7], pBh + 16 * ROWB + ko);
            LDSM_X4(bl[0], bl[1], bl[2], bl[3], pBl + ko);
            LDSM_X4(bl[4], bl[5], bl[6], bl[7], pBl + 16 * ROWB + ko);
#pragma unroll
            for (int mt = 0; mt < 2; mt++)
#pragma unroll
                for (int j = 0; j < 4; j++)
                    MMA_F16(acc[mt][j], ah + mt * 4, bh[j * 2], bh[j * 2 + 1]);
#pragma unroll
            for (int mt = 0; mt < 2; mt++)
#pragma unroll
                for (int j = 0; j < 4; j++)
                    MMA_F16(acc[mt][j], ah + mt * 4, bl[j * 2], bl[j * 2 + 1]);
        }

        // ---- finish staging next slot ----
        if (it + 1 < NKIT) {
            if (!AHALF) {
                char* ns = smem + (s ^ 1) * SLOT;
                *(uint4*)(ns + soff) = cvt8h(na0, na1);
            }
            asm volatile("cp.async.wait_group 0;" ::: "memory");
        }
        __syncthreads();
    }

    // ---- epilogue ----
    const int lrow = lane >> 2;
    const int lcol = (lane & 3) * 2;
#pragma unroll
    for (int mt = 0; mt < 2; mt++) {
#pragma unroll
        for (int j = 0; j < 4; j++) {
            const int col = colBase + wn + j * 8 + lcol;
#pragma unroll
            for (int half = 0; half < 2; half++) {
                const int row = rowBase + wm + mt * 16 + lrow + half * 8;
                float v0 = acc[mt][j][half * 2 + 0];
                float v1 = acc[mt][j][half * 2 + 1];
                if (MODE == 1) {
                    v0 = (v0 > 0.f) ? (v0 + 1.f) : __expf(v0);
                    v1 = (v1 > 0.f) ? (v1 + 1.f) : __expf(v1);
                } else if (MODE == 2) {
                    v0 += bias[col];
                    v1 += bias[col + 1];
                }
                *(float2*)(C + (size_t)row * DMODEL + col) = make_float2(v0, v1);
            }
        }
    }
}

// ---------------- KV partial: per (bh, chunk) sum_s K^T V over SEQ/NCH s ----------------
__global__ void __launch_bounds__(256)
kv_partial_kernel()
{
    const int bh = blockIdx.x;
    const int ch = blockIdx.y;
    const int b = bh >> 4, h = bh & 15;
    const int tid = threadIdx.x;

    __shared__ float Ksh[16][DK];
    __shared__ float Vsh[16][DK];

    const int e = tid & 63;
    const int dbase = (tid >> 6) * 16;

    unsigned long long acc[8];
    {
        const unsigned long long z = pack2(0.f, 0.f);
#pragma unroll
        for (int i = 0; i < 8; i++) acc[i] = z;
    }
    float ksum = 0.f;

    const int s0 = ch * (SEQ / NCH);
    const size_t base = ((size_t)b * SEQ + s0) * DMODEL + h * DK;
    const int lr = tid >> 4;
    const int lc = (tid & 15) * 4;

    for (int st = 0; st < SEQ / NCH; st += 16) {
        const size_t g = base + (size_t)(st + lr) * DMODEL + lc;
        *(float4*)&Ksh[lr][lc] = *(const float4*)(g_K + g);
        *(float4*)&Vsh[lr][lc] = *(const float4*)(g_V + g);
        __syncthreads();

#pragma unroll
        for (int r = 0; r < 16; r++) {
            const float vv = Vsh[r][e];
            const unsigned long long vvp = pack2(vv, vv);
            const ulonglong2 kA = *(const ulonglong2*)&Ksh[r][dbase];
            const ulonglong2 kB = *(const ulonglong2*)&Ksh[r][dbase + 4];
            const ulonglong2 kC = *(const ulonglong2*)&Ksh[r][dbase + 8];
            const ulonglong2 kD = *(const ulonglong2*)&Ksh[r][dbase + 12];
            ffma2(acc[0], kA.x, vvp); ffma2(acc[1], kA.y, vvp);
            ffma2(acc[2], kB.x, vvp); ffma2(acc[3], kB.y, vvp);
            ffma2(acc[4], kC.x, vvp); ffma2(acc[5], kC.y, vvp);
            ffma2(acc[6], kD.x, vvp); ffma2(acc[7], kD.y, vvp);
        }
        if (tid < 64) {
#pragma unroll
            for (int r = 0; r < 16; r++) ksum += Ksh[r][tid];
        }
        __syncthreads();
    }

    float* pkv = g_pKV + ((size_t)ch * BH + bh) * (DK * DK);
#pragma unroll
    for (int p = 0; p < 8; p++) {
        float v0, v1;
        unpack2(acc[p], v0, v1);
        pkv[(dbase + 2 * p) * DK + e] = v0;
        pkv[(dbase + 2 * p + 1) * DK + e] = v1;
    }
    if (tid < 64) g_pKsum[((size_t)ch * BH + bh) * DK + tid] = ksum;
}

// ---------------- KV reduce ----------------
__global__ void kv_reduce_kernel()
{
    const int idx = blockIdx.x * 256 + threadIdx.x;
    const int NKV = BH * DK * DK;
    if (idx < NKV) {
        float s = 0.f;
#pragma unroll
        for (int ch = 0; ch < NCH; ch++) s += g_pKV[(size_t)ch * NKV + idx];
        g_KV[idx] = s;
    } else if (idx < NKV + BH * DK) {
        const int o = idx - NKV;
        float s = 0.f;
#pragma unroll
        for (int ch = 0; ch < NCH; ch++) s += g_pKsum[(size_t)ch * BH * DK + o];
        g_Ksum[o] = s;
    }
}

// ---------------- attention apply: out = (Q @ KV) / (Q . Ksum + eps) -> fp16 ----------------
__global__ void __launch_bounds__(256)
attn_kernel()
{
    const int bh = blockIdx.x;
    const int qt = blockIdx.y;
    const int b = bh >> 4, h = bh & 15;
    const int tid = threadIdx.x;

    __shared__ float KVs[DK * DK];
    __shared__ float Qs[DK][DK + 2];
    __shared__ float Ksm[DK];
    __shared__ float rden[DK];

    const size_t base = ((size_t)b * SEQ + qt * DK) * DMODEL + h * DK;

#pragma unroll
    for (int l = 0; l < 16; l++) {
        const int idx = tid + l * 256;
        KVs[idx] = g_KV[(size_t)bh * DK * DK + idx];
        const int q = idx >> 6, d = idx & 63;
        Qs[d][q] = g_Q[base + (size_t)q * DMODEL + d];
    }
    if (tid < DK) Ksm[tid] = g_Ksum[bh * DK + tid];
    __syncthreads();

    if (tid < DK) {
        float s = 0.f;
#pragma unroll
        for (int d = 0; d < DK; d++) s += Qs[d][tid] * Ksm[d];
        rden[tid] = 1.f / (s + 1e-6f);
    }
    __syncthreads();

    const int e = tid & 63;
    const int qg = tid >> 6;

    unsigned long long acc[8];
    {
        const unsigned long long z = pack2(0.f, 0.f);
#pragma unroll
        for (int i = 0; i < 8; i++) acc[i] = z;
    }

#pragma unroll 8
    for (int d = 0; d < DK; d++) {
        const float kv = KVs[d * DK + e];
        const unsigned long long kvp = pack2(kv, kv);
#pragma unroll
        for (int t = 0; t < 8; t++) {
            const unsigned long long qp =
                *(const unsigned long long*)&Qs[d][qg * 16 + 2 * t];
            ffma2(acc[t], qp, kvp);
        }
    }

#pragma unroll
    for (int t = 0; t < 8; t++) {
        float v0, v1;
        unpack2(acc[t], v0, v1);
        const int q0 = qg * 16 + 2 * t;
        v0 *= rden[q0];
        v1 *= rden[q0 + 1];
        unsigned short h0, h1;
        asm("cvt.rn.f16.f32 %0, %1;" : "=h"(h0) : "f"(v0));
        asm("cvt.rn.f16.f32 %0, %1;" : "=h"(h1) : "f"(v1));
        g_af16[base + (size_t)q0 * DMODEL + e] = h0;
        g_af16[base + (size_t)(q0 + 1) * DMODEL + e] = h1;
    }
}

// ---------------- launch ----------------
extern "C" void kernel_launch(void* const* d_in, const int* in_sizes, int n_in,
                              void* d_out, int out_size)
{
    const float* query = (const float*)d_in[0];
    const float* key   = (const float*)d_in[1];
    const float* value = (const float*)d_in[2];
    const float* Wq    = (const float*)d_in[3];
    const float* Wk    = (const float*)d_in[4];
    const float* Wv    = (const float*)d_in[5];
    const float* Wo    = (const float*)d_in[6];
    const float* bo    = (const float*)d_in[7];
    float* out = (float*)d_out;
    (void)in_sizes; (void)n_in; (void)out_size;

    float *pQ, *pK, *pV;
    unsigned short *whi, *wlo, *af16;
    cudaGetSymbolAddress((void**)&pQ, g_Q);
    cudaGetSymbolAddress((void**)&pK, g_K);
    cudaGetSymbolAddress((void**)&pV, g_V);
    cudaGetSymbolAddress((void**)&whi, g_whi);
    cudaGetSymbolAddress((void**)&wlo, g_wlo);
    cudaGetSymbolAddress((void**)&af16, g_af16);

    cudaFuncSetAttribute(gemm_h2<0,0>, cudaFuncAttributeMaxDynamicSharedMemorySize, GEMM_SMEM);
    cudaFuncSetAttribute(gemm_h2<1,0>, cudaFuncAttributeMaxDynamicSharedMemorySize, GEMM_SMEM);
    cudaFuncSetAttribute(gemm_h2<2,1>, cudaFuncAttributeMaxDynamicSharedMemorySize, GEMM_SMEM);

    const int n4w = DMODEL * DMODEL / 4;
    const int cb = 256;
    const dim3 ggrid(DMODEL / 128, M_TOTAL / 128);   // (8, 128)

    // Q = phi(query @ Wq^T)
    cvt_wsplit_kernel<<<(n4w + cb - 1) / cb, cb>>>(Wq, whi, wlo, n4w);
    gemm_h2<1,0><<<ggrid, 512, GEMM_SMEM>>>(query, whi, wlo, pQ, nullptr);

    // K = phi(key @ Wk^T)
    cvt_wsplit_kernel<<<(n4w + cb - 1) / cb, cb>>>(Wk, whi, wlo, n4w);
    gemm_h2<1,0><<<ggrid, 512, GEMM_SMEM>>>(key, whi, wlo, pK, nullptr);

    // V = value @ Wv^T
    cvt_wsplit_kernel<<<(n4w + cb - 1) / cb, cb>>>(Wv, whi, wlo, n4w);
    gemm_h2<0,0><<<ggrid, 512, GEMM_SMEM>>>(value, whi, wlo, pV, nullptr);

    // linear attention core
    kv_partial_kernel<<<dim3(BH, NCH), 256>>>();
    kv_reduce_kernel<<<(BH * DK * DK + BH * DK + 255) / 256, 256>>>();
    attn_kernel<<<dim3(BH, SEQ / DK), 256>>>();

    // out = attn @ Wo^T + bo  (A pre-quantized fp16 by attn_kernel)
    cvt_wsplit_kernel<<<(n4w + cb - 1) / cb, cb>>>(Wo, whi, wlo, n4w);
    gemm_h2<2,1><<<ggrid, 512, GEMM_SMEM>>>(af16, whi, wlo, out, bo);
}